// round 15
// baseline (speedup 1.0000x reference)
#include <cuda_runtime.h>
#include <cuda_fp16.h>
#include <cstdint>

// ---------------------------------------------------------------- shapes
#define D_FEAT 4096
#define N_SAMP 8192
#define OUT_D  2048

// ---------------------------------------------------------------- scratch
__device__ __half g_psi_h[(size_t)OUT_D * N_SAMP];
__device__ __half g_x_h[(size_t)D_FEAT * N_SAMP];
__device__ __half g_tmp_h[(size_t)OUT_D * D_FEAT];
__device__ float g_part1[(size_t)4 * OUT_D * D_FEAT];
__device__ float g_part2[(size_t)2 * OUT_D * N_SAMP];

// ---------------------------------------------------------------- helpers
__device__ __forceinline__ uint32_t smem_u32(const void* p) {
    uint32_t a;
    asm("{ .reg .u64 t; cvta.to.shared.u64 t, %1; cvt.u32.u64 %0, t; }" : "=r"(a) : "l"(p));
    return a;
}
__device__ __forceinline__ void cpasync16(uint32_t s, const void* g) {
    asm volatile("cp.async.cg.shared.global [%0], [%1], 16;" :: "r"(s), "l"(g));
}
__device__ __forceinline__ void cp_commit() {
    asm volatile("cp.async.commit_group;" ::: "memory");
}
__device__ __forceinline__ void cp_wait1() {
    asm volatile("cp.async.wait_group 1;" ::: "memory");
}
__device__ __forceinline__ void ldsm4(uint32_t* r, uint32_t addr) {
    asm volatile("ldmatrix.sync.aligned.m8n8.x4.shared.b16 {%0,%1,%2,%3}, [%4];"
                 : "=r"(r[0]), "=r"(r[1]), "=r"(r[2]), "=r"(r[3]) : "r"(addr));
}
__device__ __forceinline__ void ldsm4t(uint32_t* r, uint32_t addr) {
    asm volatile("ldmatrix.sync.aligned.m8n8.x4.trans.shared.b16 {%0,%1,%2,%3}, [%4];"
                 : "=r"(r[0]), "=r"(r[1]), "=r"(r[2]), "=r"(r[3]) : "r"(addr));
}
__device__ __forceinline__ void mma_f16(float* c, const uint32_t* a, const uint32_t* b) {
    asm volatile("mma.sync.aligned.m16n8k16.row.col.f32.f16.f16.f32 "
                 "{%0,%1,%2,%3}, {%4,%5,%6,%7}, {%8,%9}, {%0,%1,%2,%3};"
                 : "+f"(c[0]), "+f"(c[1]), "+f"(c[2]), "+f"(c[3])
                 : "r"(a[0]), "r"(a[1]), "r"(a[2]), "r"(a[3]), "r"(b[0]), "r"(b[1]));
}
__device__ __forceinline__ uint32_t sw128(uint32_t off) {
    return off ^ ((off >> 3) & 0x70);
}

// ------------------------------------------------- fused prep
#define XCHUNKS ((D_FEAT * (N_SAMP / 4)) / 256)

__global__ void prep_kernel(const float* __restrict__ Psi, const float* __restrict__ x,
                            __half* __restrict__ ph, __half* __restrict__ xh) {
    if (blockIdx.x < OUT_D) {
        const int row = blockIdx.x;
        const float4* p = reinterpret_cast<const float4*>(Psi) + (size_t)row * (N_SAMP / 4);
        float4 v[8];
        float s = 0.f;
        #pragma unroll
        for (int q = 0; q < 8; ++q) {
            v[q] = p[q * 256 + threadIdx.x];
            s += (v[q].x + v[q].y) + (v[q].z + v[q].w);
        }
        __shared__ float red[256];
        red[threadIdx.x] = s;
        __syncthreads();
        #pragma unroll
        for (int off = 128; off > 0; off >>= 1) {
            if (threadIdx.x < off) red[threadIdx.x] += red[threadIdx.x + off];
            __syncthreads();
        }
        const float m = red[0] * (1.0f / N_SAMP);
        ushort4* hp = reinterpret_cast<ushort4*>(ph) + (size_t)row * (N_SAMP / 4);
        #pragma unroll
        for (int q = 0; q < 8; ++q) {
            float4 w = v[q];
            __half h0 = __float2half_rn(w.x - m);
            __half h1 = __float2half_rn(w.y - m);
            __half h2 = __float2half_rn(w.z - m);
            __half h3 = __float2half_rn(w.w - m);
            hp[q * 256 + threadIdx.x] = make_ushort4(
                __half_as_ushort(h0), __half_as_ushort(h1),
                __half_as_ushort(h2), __half_as_ushort(h3));
        }
    } else {
        const size_t i = (size_t)(blockIdx.x - OUT_D) * 256 + threadIdx.x;
        float4 v = reinterpret_cast<const float4*>(x)[i];
        __half h0 = __float2half_rn(v.x), h1 = __float2half_rn(v.y);
        __half h2 = __float2half_rn(v.z), h3 = __float2half_rn(v.w);
        reinterpret_cast<ushort4*>(xh)[i] = make_ushort4(
            __half_as_ushort(h0), __half_as_ushort(h1),
            __half_as_ushort(h2), __half_as_ushort(h3));
    }
}

// ---------------------------------------------------------------- fp16 GEMM (split-K)
// Cpart[z][M,N] = A[M,kz:kz+klen] * B[N-slab]^T, plain fp16, fp32 accum.
// CTA 128x128, 128 threads: 4 warps, warp tile 64x64 (2m x 2n).
// K_TILE=64, 3-stage cp.async ring (32KB/stage, 96KB/CTA, 2 CTAs/SM),
// wait_group 1: the s+1 load stays in flight through barrier + compute.
// BTRANS=0: B [N, K] K-contiguous (SW128 128B rows).
// BTRANS=1: B [K, ldb] N-contiguous (trans ldsm, two SW128 64-col subtiles).
#define STG_BYTES 32768
#define A_OFF  0
#define B_OFF  16384

template <int BTRANS>
__global__ void __launch_bounds__(128, 2)
gemm_f16(const __half* __restrict__ A, const __half* __restrict__ B,
         float* __restrict__ Cpart,
         int N, int K, int klen, int ldb) {
    extern __shared__ char smem[];
    const uint32_t sb = smem_u32(smem);

    const int tid  = threadIdx.x;
    const int wid  = tid >> 5;
    const int lane = tid & 31;
    const int wm   = wid & 1;          // 0..1 -> 64-row slab
    const int wn   = wid >> 1;         // 0..1 -> 64-col slab
    const int m0   = blockIdx.x * 128;
    const int n0   = blockIdx.y * 128;
    const int kz   = blockIdx.z * klen;
    float* C = Cpart + (size_t)blockIdx.z * ((size_t)gridDim.x * 128) * N;

    // loader: 8 chunks per array per thread (1024 x 16B per [128x64] fp16 array)
    uint32_t soffA[8], soffB[8];
    size_t gA[8], gB[8];
    #pragma unroll
    for (int q = 0; q < 8; ++q) {
        const int id = q * 128 + tid;
        {
            const int r = id >> 3, sg = id & 7;          // 128 rows x 8 chunks (128B row)
            soffA[q] = sw128((uint32_t)(r * 128 + sg * 16));
            gA[q]    = (size_t)(m0 + r) * K + kz + sg * 8;
        }
        if (BTRANS == 0) {
            const int r = id >> 3, sg = id & 7;
            soffB[q] = sw128((uint32_t)(r * 128 + sg * 16));
            gB[q]    = (size_t)(n0 + r) * (size_t)ldb + kz + sg * 8;
        } else {
            const int r = id >> 4, c = id & 15;          // 64 k-rows x 16 chunks
            const int sub = c >> 3;                       // n >= 64 -> subtile 1 (8KB)
            soffB[q] = sub * 8192 + sw128((uint32_t)(r * 128 + (c & 7) * 16));
            gB[q]    = (size_t)(kz + r) * (size_t)ldb + n0 + c * 8;
        }
    }

    auto load_stage = [&](int t) {
        const uint32_t base = sb + (t % 3) * STG_BYTES;
        const size_t ka = (size_t)t * 64;
        const size_t kb = BTRANS ? (size_t)t * 64 * (size_t)ldb : (size_t)t * 64;
        #pragma unroll
        for (int q = 0; q < 8; ++q) {
            cpasync16(base + A_OFF + soffA[q], A + gA[q] + ka);
            cpasync16(base + B_OFF + soffB[q], B + gB[q] + kb);
        }
        cp_commit();
    };

    const int quad = lane >> 3, l8 = lane & 7;
    const int a_row  = wm * 64 + (quad & 1) * 8 + l8;
    const int a_colq = (quad >> 1) * 8;
    const int b_row0 = wn * 64 + (quad >> 1) * 8 + l8;
    const int b_col0 = (quad & 1) * 8;
    const int b_kq   = (quad & 1) * 8 + l8;
    const int b_nq   = wn * 64 + (quad >> 1) * 8;

    float acc[4][8][4];   // [m16 tile i][n8 tile j][4]  = 128 regs
    #pragma unroll
    for (int i = 0; i < 4; ++i)
        #pragma unroll
        for (int j = 0; j < 8; ++j)
            #pragma unroll
            for (int e = 0; e < 4; ++e) acc[i][j][e] = 0.f;

    const int ntiles = klen / 64;
    load_stage(0);
    load_stage(1);

    for (int s = 0; s < ntiles; ++s) {
        cp_wait1();          // oldest group (stage s) landed; s+1 keeps flying
        __syncthreads();     // all warps done with stage s-1 -> its buffer (s+2)%3 reusable
        if (s + 2 < ntiles) load_stage(s + 2);

        const uint32_t st = sb + (s % 3) * STG_BYTES;
        #pragma unroll
        for (int h = 0; h < 4; ++h) {
            const int k0 = h * 16;
            uint32_t Af[4][4];
            #pragma unroll
            for (int i = 0; i < 4; ++i) {
                const uint32_t ao = sw128((uint32_t)((a_row + i * 16) * 128 + (k0 + a_colq) * 2));
                ldsm4(Af[i], st + A_OFF + ao);
            }
            uint32_t Bf[4][4];
            #pragma unroll
            for (int j = 0; j < 4; ++j) {
                uint32_t bo;
                if (BTRANS == 0) {
                    bo = sw128((uint32_t)((b_row0 + j * 16) * 128 + (k0 + b_col0) * 2));
                    ldsm4(Bf[j], st + B_OFF + bo);
                } else {
                    const int ncol = b_nq + j * 16;
                    const int sub  = ncol >> 6;
                    bo = sub * 8192 + sw128((uint32_t)((k0 + b_kq) * 128 + (ncol & 63) * 2));
                    ldsm4t(Bf[j], st + B_OFF + bo);
                }
            }
            #pragma unroll
            for (int i = 0; i < 4; ++i)
                #pragma unroll
                for (int j = 0; j < 8; ++j)
                    mma_f16(acc[i][j], Af[i], &Bf[j >> 1][(j & 1) * 2]);
        }
    }

    const int r_base = m0 + wm * 64 + (lane >> 2);
    const int c_base = n0 + wn * 64 + (lane & 3) * 2;
    #pragma unroll
    for (int i = 0; i < 4; ++i) {
        #pragma unroll
        for (int j = 0; j < 8; ++j) {
            const int r0 = r_base + i * 16;
            const int c  = c_base + j * 8;
            *reinterpret_cast<float2*>(C + (size_t)r0 * N + c) =
                make_float2(acc[i][j][0], acc[i][j][1]);
            *reinterpret_cast<float2*>(C + (size_t)(r0 + 8) * N + c) =
                make_float2(acc[i][j][2], acc[i][j][3]);
        }
    }
}

// ---------------------------------------------- reduce 4 partials -> fp16 tmp
__global__ void reduce4_kernel(const float* __restrict__ p, __half* __restrict__ h16) {
    const size_t i = (size_t)blockIdx.x * 256 + threadIdx.x;
    const size_t off = (size_t)OUT_D * D_FEAT / 4;
    const float4* pv = reinterpret_cast<const float4*>(p);
    float4 a = pv[i], b = pv[i + off], c = pv[i + 2 * off], d = pv[i + 3 * off];
    __half h0 = __float2half_rn((a.x + b.x) + (c.x + d.x));
    __half h1 = __float2half_rn((a.y + b.y) + (c.y + d.y));
    __half h2 = __float2half_rn((a.z + b.z) + (c.z + d.z));
    __half h3 = __float2half_rn((a.w + b.w) + (c.w + d.w));
    reinterpret_cast<ushort4*>(h16)[i] = make_ushort4(
        __half_as_ushort(h0), __half_as_ushort(h1),
        __half_as_ushort(h2), __half_as_ushort(h3));
}

// ---------------------------------------------- reduce 2 partials -> fp32 out
__global__ void reduce2_kernel(const float* __restrict__ p, float* __restrict__ out) {
    const size_t i = (size_t)blockIdx.x * 256 + threadIdx.x;
    const size_t off = (size_t)OUT_D * N_SAMP / 4;
    const float4* pv = reinterpret_cast<const float4*>(p);
    float4 a = pv[i], b = pv[i + off];
    reinterpret_cast<float4*>(out)[i] = make_float4(a.x + b.x, a.y + b.y, a.z + b.z, a.w + b.w);
}

// ---------------------------------------------------------------- launch
extern "C" void kernel_launch(void* const* d_in, const int* in_sizes, int n_in,
                              void* d_out, int out_size) {
    (void)n_in; (void)out_size;

    const float* x;
    const float* Psi;
    if (in_sizes[0] == D_FEAT * N_SAMP) {
        x   = (const float*)d_in[0];
        Psi = (const float*)d_in[1];
    } else {
        x   = (const float*)d_in[1];
        Psi = (const float*)d_in[0];
    }
    float* out = (float*)d_out;

    __half *psi_h, *x_h, *tmp_h;
    float *part1, *part2;
    cudaGetSymbolAddress((void**)&psi_h, g_psi_h);
    cudaGetSymbolAddress((void**)&x_h,   g_x_h);
    cudaGetSymbolAddress((void**)&tmp_h, g_tmp_h);
    cudaGetSymbolAddress((void**)&part1, g_part1);
    cudaGetSymbolAddress((void**)&part2, g_part2);

    const int SMEM_BYTES = 3 * STG_BYTES;   // 98304
    cudaFuncSetAttribute(gemm_f16<0>, cudaFuncAttributeMaxDynamicSharedMemorySize, SMEM_BYTES);
    cudaFuncSetAttribute(gemm_f16<1>, cudaFuncAttributeMaxDynamicSharedMemorySize, SMEM_BYTES);

    // 1) fused prep: Psi -> fp16 (centered), x -> fp16
    prep_kernel<<<OUT_D + XCHUNKS, 256>>>(Psi, x, psi_h, x_h);

    // 2) GEMM1 split-K4: part1[z] = psi_h . x_h  (B non-trans)
    {
        dim3 grid(OUT_D / 128, D_FEAT / 128, 4);
        gemm_f16<0><<<grid, 128, SMEM_BYTES>>>(
            psi_h, x_h, part1, D_FEAT, N_SAMP, N_SAMP / 4, N_SAMP);
    }
    reduce4_kernel<<<(OUT_D * D_FEAT / 4) / 256, 256>>>(part1, tmp_h);

    // 3) GEMM2 split-K2: part2[z] = tmp_h . x_h  (B = x in [d,n] layout, trans ldsm)
    {
        dim3 grid(OUT_D / 128, N_SAMP / 128, 2);
        gemm_f16<1><<<grid, 128, SMEM_BYTES>>>(
            tmp_h, x_h, part2, N_SAMP, D_FEAT, D_FEAT / 2, N_SAMP);
    }
    reduce2_kernel<<<(OUT_D * N_SAMP / 4) / 256, 256>>>(part2, out);
}

// round 16
// speedup vs baseline: 1.0218x; 1.0218x over previous
#include <cuda_runtime.h>
#include <cuda_fp16.h>
#include <cstdint>

// ---------------------------------------------------------------- shapes
#define D_FEAT 4096
#define N_SAMP 8192
#define OUT_D  2048

// ---------------------------------------------------------------- scratch
__device__ __half g_psi_h[(size_t)OUT_D * N_SAMP];
__device__ __half g_x_h[(size_t)D_FEAT * N_SAMP];
__device__ __half g_tmp_h[(size_t)OUT_D * D_FEAT];
__device__ float g_part1[(size_t)4 * OUT_D * D_FEAT];
__device__ float g_part2[(size_t)2 * OUT_D * N_SAMP];

// ---------------------------------------------------------------- helpers
__device__ __forceinline__ uint32_t smem_u32(const void* p) {
    uint32_t a;
    asm("{ .reg .u64 t; cvta.to.shared.u64 t, %1; cvt.u32.u64 %0, t; }" : "=r"(a) : "l"(p));
    return a;
}
__device__ __forceinline__ void cpasync16(uint32_t s, const void* g) {
    asm volatile("cp.async.cg.shared.global [%0], [%1], 16;" :: "r"(s), "l"(g));
}
__device__ __forceinline__ void cp_commit() {
    asm volatile("cp.async.commit_group;" ::: "memory");
}
__device__ __forceinline__ void cp_wait0() {
    asm volatile("cp.async.wait_group 0;" ::: "memory");
}
__device__ __forceinline__ void ldsm4(uint32_t* r, uint32_t addr) {
    asm volatile("ldmatrix.sync.aligned.m8n8.x4.shared.b16 {%0,%1,%2,%3}, [%4];"
                 : "=r"(r[0]), "=r"(r[1]), "=r"(r[2]), "=r"(r[3]) : "r"(addr));
}
__device__ __forceinline__ void ldsm4t(uint32_t* r, uint32_t addr) {
    asm volatile("ldmatrix.sync.aligned.m8n8.x4.trans.shared.b16 {%0,%1,%2,%3}, [%4];"
                 : "=r"(r[0]), "=r"(r[1]), "=r"(r[2]), "=r"(r[3]) : "r"(addr));
}
__device__ __forceinline__ void mma_f16(float* c, const uint32_t* a, const uint32_t* b) {
    asm volatile("mma.sync.aligned.m16n8k16.row.col.f32.f16.f16.f32 "
                 "{%0,%1,%2,%3}, {%4,%5,%6,%7}, {%8,%9}, {%0,%1,%2,%3};"
                 : "+f"(c[0]), "+f"(c[1]), "+f"(c[2]), "+f"(c[3])
                 : "r"(a[0]), "r"(a[1]), "r"(a[2]), "r"(a[3]), "r"(b[0]), "r"(b[1]));
}
__device__ __forceinline__ uint32_t sw128(uint32_t off) {
    return off ^ ((off >> 3) & 0x70);
}

// ------------------------------------------------- fused prep
#define XCHUNKS ((D_FEAT * (N_SAMP / 4)) / 256)

__global__ void prep_kernel(const float* __restrict__ Psi, const float* __restrict__ x,
                            __half* __restrict__ ph, __half* __restrict__ xh) {
    if (blockIdx.x < OUT_D) {
        const int row = blockIdx.x;
        const float4* p = reinterpret_cast<const float4*>(Psi) + (size_t)row * (N_SAMP / 4);
        float4 v[8];
        float s = 0.f;
        #pragma unroll
        for (int q = 0; q < 8; ++q) {
            v[q] = p[q * 256 + threadIdx.x];
            s += (v[q].x + v[q].y) + (v[q].z + v[q].w);
        }
        __shared__ float red[256];
        red[threadIdx.x] = s;
        __syncthreads();
        #pragma unroll
        for (int off = 128; off > 0; off >>= 1) {
            if (threadIdx.x < off) red[threadIdx.x] += red[threadIdx.x + off];
            __syncthreads();
        }
        const float m = red[0] * (1.0f / N_SAMP);
        ushort4* hp = reinterpret_cast<ushort4*>(ph) + (size_t)row * (N_SAMP / 4);
        #pragma unroll
        for (int q = 0; q < 8; ++q) {
            float4 w = v[q];
            __half h0 = __float2half_rn(w.x - m);
            __half h1 = __float2half_rn(w.y - m);
            __half h2 = __float2half_rn(w.z - m);
            __half h3 = __float2half_rn(w.w - m);
            hp[q * 256 + threadIdx.x] = make_ushort4(
                __half_as_ushort(h0), __half_as_ushort(h1),
                __half_as_ushort(h2), __half_as_ushort(h3));
        }
    } else {
        const size_t i = (size_t)(blockIdx.x - OUT_D) * 256 + threadIdx.x;
        float4 v = reinterpret_cast<const float4*>(x)[i];
        __half h0 = __float2half_rn(v.x), h1 = __float2half_rn(v.y);
        __half h2 = __float2half_rn(v.z), h3 = __float2half_rn(v.w);
        reinterpret_cast<ushort4*>(xh)[i] = make_ushort4(
            __half_as_ushort(h0), __half_as_ushort(h1),
            __half_as_ushort(h2), __half_as_ushort(h3));
    }
}

// ---------------------------------------------------------------- fp16 GEMM (split-K)
// Cpart[z][M,N] = A[M,kz:kz+klen] * B[N-slab]^T, plain fp16, fp32 accum.
// CTA 128x128, 128 threads: 4 warps, warp tile 64x64 (2m x 2n).
// 8 ldsm.x4 per 32 MMAs per k16 (0.25 ldsm/MMA). K_TILE=64, 2-stage ring
// (32KB/stage, 64KB/CTA, 2 CTAs/SM), one barrier per k64 tile.
// BTRANS=0: B [N, K] K-contiguous (SW128 128B rows).
// BTRANS=1: B [K, ldb] N-contiguous (trans ldsm, two SW128 64-col subtiles).
#define STG_BYTES 32768
#define A_OFF  0
#define B_OFF  16384

template <int BTRANS>
__global__ void __launch_bounds__(128, 2)
gemm_f16(const __half* __restrict__ A, const __half* __restrict__ B,
         float* __restrict__ Cpart,
         int N, int K, int klen, int ldb) {
    extern __shared__ char smem[];
    const uint32_t sb = smem_u32(smem);

    const int tid  = threadIdx.x;
    const int wid  = tid >> 5;
    const int lane = tid & 31;
    const int wm   = wid & 1;          // 0..1 -> 64-row slab
    const int wn   = wid >> 1;         // 0..1 -> 64-col slab
    const int m0   = blockIdx.x * 128;
    const int n0   = blockIdx.y * 128;
    const int kz   = blockIdx.z * klen;
    float* C = Cpart + (size_t)blockIdx.z * ((size_t)gridDim.x * 128) * N;

    // loader: 8 chunks per array per thread (1024 x 16B per [128x64] fp16 array)
    uint32_t soffA[8], soffB[8];
    size_t gA[8], gB[8];
    #pragma unroll
    for (int q = 0; q < 8; ++q) {
        const int id = q * 128 + tid;
        {
            const int r = id >> 3, sg = id & 7;          // 128 rows x 8 chunks (128B row)
            soffA[q] = sw128((uint32_t)(r * 128 + sg * 16));
            gA[q]    = (size_t)(m0 + r) * K + kz + sg * 8;
        }
        if (BTRANS == 0) {
            const int r = id >> 3, sg = id & 7;
            soffB[q] = sw128((uint32_t)(r * 128 + sg * 16));
            gB[q]    = (size_t)(n0 + r) * (size_t)ldb + kz + sg * 8;
        } else {
            const int r = id >> 4, c = id & 15;          // 64 k-rows x 16 chunks
            const int sub = c >> 3;                       // n >= 64 -> subtile 1 (8KB)
            soffB[q] = sub * 8192 + sw128((uint32_t)(r * 128 + (c & 7) * 16));
            gB[q]    = (size_t)(kz + r) * (size_t)ldb + n0 + c * 8;
        }
    }

    auto load_stage = [&](int t) {
        const uint32_t base = sb + (t & 1) * STG_BYTES;
        const size_t ka = (size_t)t * 64;
        const size_t kb = BTRANS ? (size_t)t * 64 * (size_t)ldb : (size_t)t * 64;
        #pragma unroll
        for (int q = 0; q < 8; ++q) {
            cpasync16(base + A_OFF + soffA[q], A + gA[q] + ka);
            cpasync16(base + B_OFF + soffB[q], B + gB[q] + kb);
        }
        cp_commit();
    };

    const int quad = lane >> 3, l8 = lane & 7;
    const int a_row  = wm * 64 + (quad & 1) * 8 + l8;
    const int a_colq = (quad >> 1) * 8;
    const int b_row0 = wn * 64 + (quad >> 1) * 8 + l8;
    const int b_col0 = (quad & 1) * 8;
    const int b_kq   = (quad & 1) * 8 + l8;
    const int b_nq   = wn * 64 + (quad >> 1) * 8;

    float acc[4][8][4];   // [m16 tile i][n8 tile j][4]  = 128 regs
    #pragma unroll
    for (int i = 0; i < 4; ++i)
        #pragma unroll
        for (int j = 0; j < 8; ++j)
            #pragma unroll
            for (int e = 0; e < 4; ++e) acc[i][j][e] = 0.f;

    const int ntiles = klen / 64;
    load_stage(0);

    for (int s = 0; s < ntiles; ++s) {
        cp_wait0();          // stage s resident
        __syncthreads();     // all warps done with stage s-1 -> safe to overwrite
        if (s + 1 < ntiles) load_stage(s + 1);

        const uint32_t st = sb + (s & 1) * STG_BYTES;
        #pragma unroll
        for (int h = 0; h < 4; ++h) {
            const int k0 = h * 16;
            uint32_t Af[4][4];
            #pragma unroll
            for (int i = 0; i < 4; ++i) {
                const uint32_t ao = sw128((uint32_t)((a_row + i * 16) * 128 + (k0 + a_colq) * 2));
                ldsm4(Af[i], st + A_OFF + ao);
            }
            uint32_t Bf[4][4];
            #pragma unroll
            for (int j = 0; j < 4; ++j) {
                uint32_t bo;
                if (BTRANS == 0) {
                    bo = sw128((uint32_t)((b_row0 + j * 16) * 128 + (k0 + b_col0) * 2));
                    ldsm4(Bf[j], st + B_OFF + bo);
                } else {
                    const int ncol = b_nq + j * 16;
                    const int sub  = ncol >> 6;
                    bo = sub * 8192 + sw128((uint32_t)((k0 + b_kq) * 128 + (ncol & 63) * 2));
                    ldsm4t(Bf[j], st + B_OFF + bo);
                }
            }
            #pragma unroll
            for (int i = 0; i < 4; ++i)
                #pragma unroll
                for (int j = 0; j < 8; ++j)
                    mma_f16(acc[i][j], Af[i], &Bf[j >> 1][(j & 1) * 2]);
        }
    }

    const int r_base = m0 + wm * 64 + (lane >> 2);
    const int c_base = n0 + wn * 64 + (lane & 3) * 2;
    #pragma unroll
    for (int i = 0; i < 4; ++i) {
        #pragma unroll
        for (int j = 0; j < 8; ++j) {
            const int r0 = r_base + i * 16;
            const int c  = c_base + j * 8;
            *reinterpret_cast<float2*>(C + (size_t)r0 * N + c) =
                make_float2(acc[i][j][0], acc[i][j][1]);
            *reinterpret_cast<float2*>(C + (size_t)(r0 + 8) * N + c) =
                make_float2(acc[i][j][2], acc[i][j][3]);
        }
    }
}

// ---------------------------------------------- reduce 4 partials -> fp16 tmp
__global__ void reduce4_kernel(const float* __restrict__ p, __half* __restrict__ h16) {
    const size_t i = (size_t)blockIdx.x * 256 + threadIdx.x;
    const size_t off = (size_t)OUT_D * D_FEAT / 4;
    const float4* pv = reinterpret_cast<const float4*>(p);
    float4 a = pv[i], b = pv[i + off], c = pv[i + 2 * off], d = pv[i + 3 * off];
    __half h0 = __float2half_rn((a.x + b.x) + (c.x + d.x));
    __half h1 = __float2half_rn((a.y + b.y) + (c.y + d.y));
    __half h2 = __float2half_rn((a.z + b.z) + (c.z + d.z));
    __half h3 = __float2half_rn((a.w + b.w) + (c.w + d.w));
    reinterpret_cast<ushort4*>(h16)[i] = make_ushort4(
        __half_as_ushort(h0), __half_as_ushort(h1),
        __half_as_ushort(h2), __half_as_ushort(h3));
}

// ---------------------------------------------- reduce 2 partials -> fp32 out
__global__ void reduce2_kernel(const float* __restrict__ p, float* __restrict__ out) {
    const size_t i = (size_t)blockIdx.x * 256 + threadIdx.x;
    const size_t off = (size_t)OUT_D * N_SAMP / 4;
    const float4* pv = reinterpret_cast<const float4*>(p);
    float4 a = pv[i], b = pv[i + off];
    reinterpret_cast<float4*>(out)[i] = make_float4(a.x + b.x, a.y + b.y, a.z + b.z, a.w + b.w);
}

// ---------------------------------------------------------------- launch
extern "C" void kernel_launch(void* const* d_in, const int* in_sizes, int n_in,
                              void* d_out, int out_size) {
    (void)n_in; (void)out_size;

    const float* x;
    const float* Psi;
    if (in_sizes[0] == D_FEAT * N_SAMP) {
        x   = (const float*)d_in[0];
        Psi = (const float*)d_in[1];
    } else {
        x   = (const float*)d_in[1];
        Psi = (const float*)d_in[0];
    }
    float* out = (float*)d_out;

    __half *psi_h, *x_h, *tmp_h;
    float *part1, *part2;
    cudaGetSymbolAddress((void**)&psi_h, g_psi_h);
    cudaGetSymbolAddress((void**)&x_h,   g_x_h);
    cudaGetSymbolAddress((void**)&tmp_h, g_tmp_h);
    cudaGetSymbolAddress((void**)&part1, g_part1);
    cudaGetSymbolAddress((void**)&part2, g_part2);

    const int SMEM_BYTES = 2 * STG_BYTES;   // 65536
    cudaFuncSetAttribute(gemm_f16<0>, cudaFuncAttributeMaxDynamicSharedMemorySize, SMEM_BYTES);
    cudaFuncSetAttribute(gemm_f16<1>, cudaFuncAttributeMaxDynamicSharedMemorySize, SMEM_BYTES);

    // 1) fused prep: Psi -> fp16 (centered), x -> fp16
    prep_kernel<<<OUT_D + XCHUNKS, 256>>>(Psi, x, psi_h, x_h);

    // 2) GEMM1 split-K4: part1[z] = psi_h . x_h  (B non-trans)
    {
        dim3 grid(OUT_D / 128, D_FEAT / 128, 4);
        gemm_f16<0><<<grid, 128, SMEM_BYTES>>>(
            psi_h, x_h, part1, D_FEAT, N_SAMP, N_SAMP / 4, N_SAMP);
    }
    reduce4_kernel<<<(OUT_D * D_FEAT / 4) / 256, 256>>>(part1, tmp_h);

    // 3) GEMM2 split-K2: part2[z] = tmp_h . x_h  (B = x in [d,n] layout, trans ldsm)
    {
        dim3 grid(OUT_D / 128, N_SAMP / 128, 2);
        gemm_f16<1><<<grid, 128, SMEM_BYTES>>>(
            tmp_h, x_h, part2, N_SAMP, D_FEAT, D_FEAT / 2, N_SAMP);
    }
    reduce2_kernel<<<(OUT_D * N_SAMP / 4) / 256, 256>>>(part2, out);
}

// round 17
// speedup vs baseline: 1.0485x; 1.0262x over previous
#include <cuda_runtime.h>
#include <cuda_fp16.h>
#include <cstdint>

// ---------------------------------------------------------------- shapes
#define D_FEAT 4096
#define N_SAMP 8192
#define OUT_D  2048

// ---------------------------------------------------------------- scratch
__device__ __half g_psi_h[(size_t)OUT_D * N_SAMP];
__device__ __half g_x_h[(size_t)D_FEAT * N_SAMP];
__device__ __half g_tmp_h[(size_t)OUT_D * D_FEAT];
__device__ __half g_part1[(size_t)4 * OUT_D * D_FEAT];
__device__ __half g_part2[(size_t)2 * OUT_D * N_SAMP];

// ---------------------------------------------------------------- helpers
__device__ __forceinline__ uint32_t smem_u32(const void* p) {
    uint32_t a;
    asm("{ .reg .u64 t; cvta.to.shared.u64 t, %1; cvt.u32.u64 %0, t; }" : "=r"(a) : "l"(p));
    return a;
}
__device__ __forceinline__ void cpasync16(uint32_t s, const void* g) {
    asm volatile("cp.async.cg.shared.global [%0], [%1], 16;" :: "r"(s), "l"(g));
}
__device__ __forceinline__ void cp_commit() {
    asm volatile("cp.async.commit_group;" ::: "memory");
}
__device__ __forceinline__ void cp_wait0() {
    asm volatile("cp.async.wait_group 0;" ::: "memory");
}
__device__ __forceinline__ void ldsm4(uint32_t* r, uint32_t addr) {
    asm volatile("ldmatrix.sync.aligned.m8n8.x4.shared.b16 {%0,%1,%2,%3}, [%4];"
                 : "=r"(r[0]), "=r"(r[1]), "=r"(r[2]), "=r"(r[3]) : "r"(addr));
}
__device__ __forceinline__ void ldsm4t(uint32_t* r, uint32_t addr) {
    asm volatile("ldmatrix.sync.aligned.m8n8.x4.trans.shared.b16 {%0,%1,%2,%3}, [%4];"
                 : "=r"(r[0]), "=r"(r[1]), "=r"(r[2]), "=r"(r[3]) : "r"(addr));
}
__device__ __forceinline__ void mma_f16(float* c, const uint32_t* a, const uint32_t* b) {
    asm volatile("mma.sync.aligned.m16n8k16.row.col.f32.f16.f16.f32 "
                 "{%0,%1,%2,%3}, {%4,%5,%6,%7}, {%8,%9}, {%0,%1,%2,%3};"
                 : "+f"(c[0]), "+f"(c[1]), "+f"(c[2]), "+f"(c[3])
                 : "r"(a[0]), "r"(a[1]), "r"(a[2]), "r"(a[3]), "r"(b[0]), "r"(b[1]));
}
__device__ __forceinline__ uint32_t sw128(uint32_t off) {
    return off ^ ((off >> 3) & 0x70);
}

// ------------------------------------------------- fused prep
#define XCHUNKS ((D_FEAT * (N_SAMP / 4)) / 256)

__global__ void prep_kernel(const float* __restrict__ Psi, const float* __restrict__ x,
                            __half* __restrict__ ph, __half* __restrict__ xh) {
    if (blockIdx.x < OUT_D) {
        const int row = blockIdx.x;
        const float4* p = reinterpret_cast<const float4*>(Psi) + (size_t)row * (N_SAMP / 4);
        float4 v[8];
        float s = 0.f;
        #pragma unroll
        for (int q = 0; q < 8; ++q) {
            v[q] = p[q * 256 + threadIdx.x];
            s += (v[q].x + v[q].y) + (v[q].z + v[q].w);
        }
        __shared__ float red[256];
        red[threadIdx.x] = s;
        __syncthreads();
        #pragma unroll
        for (int off = 128; off > 0; off >>= 1) {
            if (threadIdx.x < off) red[threadIdx.x] += red[threadIdx.x + off];
            __syncthreads();
        }
        const float m = red[0] * (1.0f / N_SAMP);
        ushort4* hp = reinterpret_cast<ushort4*>(ph) + (size_t)row * (N_SAMP / 4);
        #pragma unroll
        for (int q = 0; q < 8; ++q) {
            float4 w = v[q];
            __half h0 = __float2half_rn(w.x - m);
            __half h1 = __float2half_rn(w.y - m);
            __half h2 = __float2half_rn(w.z - m);
            __half h3 = __float2half_rn(w.w - m);
            hp[q * 256 + threadIdx.x] = make_ushort4(
                __half_as_ushort(h0), __half_as_ushort(h1),
                __half_as_ushort(h2), __half_as_ushort(h3));
        }
    } else {
        const size_t i = (size_t)(blockIdx.x - OUT_D) * 256 + threadIdx.x;
        float4 v = reinterpret_cast<const float4*>(x)[i];
        __half h0 = __float2half_rn(v.x), h1 = __float2half_rn(v.y);
        __half h2 = __float2half_rn(v.z), h3 = __float2half_rn(v.w);
        reinterpret_cast<ushort4*>(xh)[i] = make_ushort4(
            __half_as_ushort(h0), __half_as_ushort(h1),
            __half_as_ushort(h2), __half_as_ushort(h3));
    }
}

// ---------------------------------------------------------------- fp16 GEMM (split-K)
// Cpart[z][M,N] = A[M,kz:kz+klen] * B[N-slab]^T, plain fp16, fp32 accum,
// fp16 partial stores (each z-slice rounded once; error ~2^-12 of the sum).
// CTA 128x128, 128 threads: 4 warps, warp tile 64x64 (2m x 2n).
// K_TILE=64, 2-stage ring (32KB/stage, 64KB/CTA, 2 CTAs/SM), one barrier/k64.
// BTRANS=0: B [N, K] K-contiguous (SW128 128B rows).
// BTRANS=1: B [K, ldb] N-contiguous (trans ldsm, two SW128 64-col subtiles).
#define STG_BYTES 32768
#define A_OFF  0
#define B_OFF  16384

template <int BTRANS>
__global__ void __launch_bounds__(128, 2)
gemm_f16(const __half* __restrict__ A, const __half* __restrict__ B,
         __half* __restrict__ Cpart,
         int N, int K, int klen, int ldb) {
    extern __shared__ char smem[];
    const uint32_t sb = smem_u32(smem);

    const int tid  = threadIdx.x;
    const int wid  = tid >> 5;
    const int lane = tid & 31;
    const int wm   = wid & 1;          // 0..1 -> 64-row slab
    const int wn   = wid >> 1;         // 0..1 -> 64-col slab
    const int m0   = blockIdx.x * 128;
    const int n0   = blockIdx.y * 128;
    const int kz   = blockIdx.z * klen;
    __half* C = Cpart + (size_t)blockIdx.z * ((size_t)gridDim.x * 128) * N;

    // loader: 8 chunks per array per thread (1024 x 16B per [128x64] fp16 array)
    uint32_t soffA[8], soffB[8];
    size_t gA[8], gB[8];
    #pragma unroll
    for (int q = 0; q < 8; ++q) {
        const int id = q * 128 + tid;
        {
            const int r = id >> 3, sg = id & 7;          // 128 rows x 8 chunks (128B row)
            soffA[q] = sw128((uint32_t)(r * 128 + sg * 16));
            gA[q]    = (size_t)(m0 + r) * K + kz + sg * 8;
        }
        if (BTRANS == 0) {
            const int r = id >> 3, sg = id & 7;
            soffB[q] = sw128((uint32_t)(r * 128 + sg * 16));
            gB[q]    = (size_t)(n0 + r) * (size_t)ldb + kz + sg * 8;
        } else {
            const int r = id >> 4, c = id & 15;          // 64 k-rows x 16 chunks
            const int sub = c >> 3;                       // n >= 64 -> subtile 1 (8KB)
            soffB[q] = sub * 8192 + sw128((uint32_t)(r * 128 + (c & 7) * 16));
            gB[q]    = (size_t)(kz + r) * (size_t)ldb + n0 + c * 8;
        }
    }

    auto load_stage = [&](int t) {
        const uint32_t base = sb + (t & 1) * STG_BYTES;
        const size_t ka = (size_t)t * 64;
        const size_t kb = BTRANS ? (size_t)t * 64 * (size_t)ldb : (size_t)t * 64;
        #pragma unroll
        for (int q = 0; q < 8; ++q) {
            cpasync16(base + A_OFF + soffA[q], A + gA[q] + ka);
            cpasync16(base + B_OFF + soffB[q], B + gB[q] + kb);
        }
        cp_commit();
    };

    const int quad = lane >> 3, l8 = lane & 7;
    const int a_row  = wm * 64 + (quad & 1) * 8 + l8;
    const int a_colq = (quad >> 1) * 8;
    const int b_row0 = wn * 64 + (quad >> 1) * 8 + l8;
    const int b_col0 = (quad & 1) * 8;
    const int b_kq   = (quad & 1) * 8 + l8;
    const int b_nq   = wn * 64 + (quad >> 1) * 8;

    float acc[4][8][4];   // [m16 tile i][n8 tile j][4]  = 128 regs
    #pragma unroll
    for (int i = 0; i < 4; ++i)
        #pragma unroll
        for (int j = 0; j < 8; ++j)
            #pragma unroll
            for (int e = 0; e < 4; ++e) acc[i][j][e] = 0.f;

    const int ntiles = klen / 64;
    load_stage(0);

    for (int s = 0; s < ntiles; ++s) {
        cp_wait0();          // stage s resident
        __syncthreads();     // all warps done with stage s-1 -> safe to overwrite
        if (s + 1 < ntiles) load_stage(s + 1);

        const uint32_t st = sb + (s & 1) * STG_BYTES;
        #pragma unroll
        for (int h = 0; h < 4; ++h) {
            const int k0 = h * 16;
            uint32_t Af[4][4];
            #pragma unroll
            for (int i = 0; i < 4; ++i) {
                const uint32_t ao = sw128((uint32_t)((a_row + i * 16) * 128 + (k0 + a_colq) * 2));
                ldsm4(Af[i], st + A_OFF + ao);
            }
            uint32_t Bf[4][4];
            #pragma unroll
            for (int j = 0; j < 4; ++j) {
                uint32_t bo;
                if (BTRANS == 0) {
                    bo = sw128((uint32_t)((b_row0 + j * 16) * 128 + (k0 + b_col0) * 2));
                    ldsm4(Bf[j], st + B_OFF + bo);
                } else {
                    const int ncol = b_nq + j * 16;
                    const int sub  = ncol >> 6;
                    bo = sub * 8192 + sw128((uint32_t)((k0 + b_kq) * 128 + (ncol & 63) * 2));
                    ldsm4t(Bf[j], st + B_OFF + bo);
                }
            }
            #pragma unroll
            for (int i = 0; i < 4; ++i)
                #pragma unroll
                for (int j = 0; j < 8; ++j)
                    mma_f16(acc[i][j], Af[i], &Bf[j >> 1][(j & 1) * 2]);
        }
    }

    // ---- epilogue: fp16 partial stores (half traffic vs fp32)
    const int r_base = m0 + wm * 64 + (lane >> 2);
    const int c_base = n0 + wn * 64 + (lane & 3) * 2;
    #pragma unroll
    for (int i = 0; i < 4; ++i) {
        #pragma unroll
        for (int j = 0; j < 8; ++j) {
            const int r0 = r_base + i * 16;
            const int c  = c_base + j * 8;
            *reinterpret_cast<__half2*>(C + (size_t)r0 * N + c) =
                __floats2half2_rn(acc[i][j][0], acc[i][j][1]);
            *reinterpret_cast<__half2*>(C + (size_t)(r0 + 8) * N + c) =
                __floats2half2_rn(acc[i][j][2], acc[i][j][3]);
        }
    }
}

// ---------------------------------------------- reduce 4 fp16 partials -> fp16 tmp
__global__ void reduce4_kernel(const __half* __restrict__ p, __half* __restrict__ h16) {
    const size_t i = (size_t)blockIdx.x * 256 + threadIdx.x;   // ushort4 index
    const size_t off = (size_t)OUT_D * D_FEAT / 4;
    const ushort4* pv = reinterpret_cast<const ushort4*>(p);
    ushort4 a = pv[i], b = pv[i + off], c = pv[i + 2 * off], d = pv[i + 3 * off];
    float s0 = (__half2float(__ushort_as_half(a.x)) + __half2float(__ushort_as_half(b.x)))
             + (__half2float(__ushort_as_half(c.x)) + __half2float(__ushort_as_half(d.x)));
    float s1 = (__half2float(__ushort_as_half(a.y)) + __half2float(__ushort_as_half(b.y)))
             + (__half2float(__ushort_as_half(c.y)) + __half2float(__ushort_as_half(d.y)));
    float s2 = (__half2float(__ushort_as_half(a.z)) + __half2float(__ushort_as_half(b.z)))
             + (__half2float(__ushort_as_half(c.z)) + __half2float(__ushort_as_half(d.z)));
    float s3 = (__half2float(__ushort_as_half(a.w)) + __half2float(__ushort_as_half(b.w)))
             + (__half2float(__ushort_as_half(c.w)) + __half2float(__ushort_as_half(d.w)));
    reinterpret_cast<ushort4*>(h16)[i] = make_ushort4(
        __half_as_ushort(__float2half_rn(s0)), __half_as_ushort(__float2half_rn(s1)),
        __half_as_ushort(__float2half_rn(s2)), __half_as_ushort(__float2half_rn(s3)));
}

// ---------------------------------------------- reduce 2 fp16 partials -> fp32 out
__global__ void reduce2_kernel(const __half* __restrict__ p, float* __restrict__ out) {
    const size_t i = (size_t)blockIdx.x * 256 + threadIdx.x;   // ushort4 index
    const size_t off = (size_t)OUT_D * N_SAMP / 4;
    const ushort4* pv = reinterpret_cast<const ushort4*>(p);
    ushort4 a = pv[i], b = pv[i + off];
    reinterpret_cast<float4*>(out)[i] = make_float4(
        __half2float(__ushort_as_half(a.x)) + __half2float(__ushort_as_half(b.x)),
        __half2float(__ushort_as_half(a.y)) + __half2float(__ushort_as_half(b.y)),
        __half2float(__ushort_as_half(a.z)) + __half2float(__ushort_as_half(b.z)),
        __half2float(__ushort_as_half(a.w)) + __half2float(__ushort_as_half(b.w)));
}

// ---------------------------------------------------------------- launch
extern "C" void kernel_launch(void* const* d_in, const int* in_sizes, int n_in,
                              void* d_out, int out_size) {
    (void)n_in; (void)out_size;

    const float* x;
    const float* Psi;
    if (in_sizes[0] == D_FEAT * N_SAMP) {
        x   = (const float*)d_in[0];
        Psi = (const float*)d_in[1];
    } else {
        x   = (const float*)d_in[1];
        Psi = (const float*)d_in[0];
    }
    float* out = (float*)d_out;

    __half *psi_h, *x_h, *tmp_h, *part1, *part2;
    cudaGetSymbolAddress((void**)&psi_h, g_psi_h);
    cudaGetSymbolAddress((void**)&x_h,   g_x_h);
    cudaGetSymbolAddress((void**)&tmp_h, g_tmp_h);
    cudaGetSymbolAddress((void**)&part1, g_part1);
    cudaGetSymbolAddress((void**)&part2, g_part2);

    const int SMEM_BYTES = 2 * STG_BYTES;   // 65536
    cudaFuncSetAttribute(gemm_f16<0>, cudaFuncAttributeMaxDynamicSharedMemorySize, SMEM_BYTES);
    cudaFuncSetAttribute(gemm_f16<1>, cudaFuncAttributeMaxDynamicSharedMemorySize, SMEM_BYTES);

    // 1) fused prep: Psi -> fp16 (centered), x -> fp16
    prep_kernel<<<OUT_D + XCHUNKS, 256>>>(Psi, x, psi_h, x_h);

    // 2) GEMM1 split-K4: part1[z] = psi_h . x_h  (B non-trans)
    {
        dim3 grid(OUT_D / 128, D_FEAT / 128, 4);
        gemm_f16<0><<<grid, 128, SMEM_BYTES>>>(
            psi_h, x_h, part1, D_FEAT, N_SAMP, N_SAMP / 4, N_SAMP);
    }
    reduce4_kernel<<<(OUT_D * D_FEAT / 4) / 256, 256>>>(part1, tmp_h);

    // 3) GEMM2 split-K2: part2[z] = tmp_h . x_h  (B = x in [d,n] layout, trans ldsm)
    {
        dim3 grid(OUT_D / 128, N_SAMP / 128, 2);
        gemm_f16<1><<<grid, 128, SMEM_BYTES>>>(
            tmp_h, x_h, part2, N_SAMP, D_FEAT, D_FEAT / 2, N_SAMP);
    }
    reduce2_kernel<<<(OUT_D * N_SAMP / 4) / 256, 256>>>(part2, out);
}